// round 1
// baseline (speedup 1.0000x reference)
#include <cuda_runtime.h>
#include <math.h>

// ---------------------------------------------------------------------------
// Problem constants
//  B=4096, SEQ=C=8, D=4, L=2048, NK=256, NCLS=100
//  filters: w3 (256,3,2048), w4 (256,4,2048), w5 (256,5,2048) -> 3072 rows
//  feature layout: K=3 off 0 (P=6), K=4 off 1536 (P=5), K=5 off 2816 (P=4)
// ---------------------------------------------------------------------------

#define NKK 3072           // total filter rows (n*12 + kk), kk: 0-2 K3, 3-6 K4, 7-11 K5
#define NCLS 100

// Scratch (device globals; no allocations allowed)
__device__ float g_WeF[5 * NKK];      // [d][nkk]; d=4 holds be-projection
__device__ float g_V[8 * 16 * NCLS]; // per (position h, code j) logit contribution
__device__ int   g_x64;              // 1 if x is int64, 0 if int32

// ---------------------------------------------------------------------------
// K1: WeF[d][nkk] = sum_l {We[d,:],be}[l] * w_row[nkk][l]
//     Also zeroes g_V and detects x dtype.
//     96 blocks x 256 threads; each warp handles 4 filter rows.
// ---------------------------------------------------------------------------
__global__ void k1_wef(const float* __restrict__ We, const float* __restrict__ be,
                       const float* __restrict__ w3, const float* __restrict__ w4,
                       const float* __restrict__ w5, const void* __restrict__ xraw)
{
    __shared__ float sW[5 * 2048];
    const int tid = threadIdx.x;

    if (blockIdx.x == 0 && tid == 0) {
        // int64 layout -> odd int32 words are all zero (values in [0,1500))
        const int* xi = (const int*)xraw;
        int any = 0;
        #pragma unroll 1
        for (int i = 1; i < 256; i += 2) any |= xi[i];
        g_x64 = (any == 0) ? 1 : 0;
    }

    int gz = blockIdx.x * blockDim.x + tid;
    if (gz < 8 * 16 * NCLS) g_V[gz] = 0.f;

    for (int i = tid; i < 2048; i += 256) {
        sW[i]            = We[i];
        sW[2048 + i]     = We[2048 + i];
        sW[2 * 2048 + i] = We[2 * 2048 + i];
        sW[3 * 2048 + i] = We[3 * 2048 + i];
        sW[4 * 2048 + i] = be[i];
    }
    __syncthreads();

    const int warp = tid >> 5, lane = tid & 31;
    const int rbase = blockIdx.x * 32 + warp * 4;

    const float* rp[4];
    #pragma unroll
    for (int r = 0; r < 4; r++) {
        int rid = rbase + r;
        int n = rid / 12, kk = rid % 12;
        if (kk < 3)      rp[r] = w3 + (size_t)(n * 3 + kk) * 2048;
        else if (kk < 7) rp[r] = w4 + (size_t)(n * 4 + (kk - 3)) * 2048;
        else             rp[r] = w5 + (size_t)(n * 5 + (kk - 7)) * 2048;
    }

    float acc[4][5];
    #pragma unroll
    for (int r = 0; r < 4; r++)
        #pragma unroll
        for (int d = 0; d < 5; d++) acc[r][d] = 0.f;

    #pragma unroll 4
    for (int i = 0; i < 64; i++) {
        int l = lane + 32 * i;
        float f[4];
        #pragma unroll
        for (int r = 0; r < 4; r++) f[r] = rp[r][l];
        float s[5];
        #pragma unroll
        for (int d = 0; d < 5; d++) s[d] = sW[d * 2048 + l];
        #pragma unroll
        for (int r = 0; r < 4; r++)
            #pragma unroll
            for (int d = 0; d < 5; d++) acc[r][d] += f[r] * s[d];
    }

    #pragma unroll
    for (int r = 0; r < 4; r++)
        #pragma unroll
        for (int d = 0; d < 5; d++)
            #pragma unroll
            for (int off = 16; off > 0; off >>= 1)
                acc[r][d] += __shfl_down_sync(0xffffffffu, acc[r][d], off);

    if (lane == 0) {
        #pragma unroll
        for (int r = 0; r < 4; r++) {
            int rid = rbase + r;
            #pragma unroll
            for (int d = 0; d < 5; d++) g_WeF[d * NKK + rid] = acc[r][d];
        }
    }
}

// ---------------------------------------------------------------------------
// K2: V[c][j][cls] += sum over valid (kk, p=c-k), n-chunk of
//        relu(LUT[c,j,:].WeF[:,nkk] + WeF[4,nkk]) * W2[feat(K,n,p), cls]
//     128 blocks = 8 c x 16 n-chunks(16 each); 128 threads (thread = cls).
// ---------------------------------------------------------------------------
__global__ void k2_v(const float* __restrict__ LUT, const float* __restrict__ W2)
{
    __shared__ float sr[192 * 16];   // [n_local*12 + kk][j]
    __shared__ float sLUT[64];       // LUT[c][j][d]
    const int tid = threadIdx.x;     // 128
    const int c  = blockIdx.x >> 4;
    const int n0 = (blockIdx.x & 15) * 16;

    if (tid < 64) sLUT[tid] = LUT[c * 64 + tid];
    __syncthreads();

    for (int pr = tid; pr < 192; pr += 128) {
        int nl = pr / 12, kk = pr % 12;
        int nkk = (n0 + nl) * 12 + kk;
        float v0 = g_WeF[nkk];
        float v1 = g_WeF[NKK + nkk];
        float v2 = g_WeF[2 * NKK + nkk];
        float v3 = g_WeF[3 * NKK + nkk];
        float v4 = g_WeF[4 * NKK + nkk];
        #pragma unroll
        for (int j = 0; j < 16; j++) {
            float r = sLUT[j * 4] * v0 + sLUT[j * 4 + 1] * v1 +
                      sLUT[j * 4 + 2] * v2 + sLUT[j * 4 + 3] * v3 + v4;
            sr[pr * 16 + j] = fmaxf(r, 0.f);
        }
    }
    __syncthreads();

    if (tid < NCLS) {
        const int cls = tid;
        float vac[16];
        #pragma unroll
        for (int j = 0; j < 16; j++) vac[j] = 0.f;

        #pragma unroll
        for (int K = 3; K <= 5; K++) {
            const int off = (K == 3) ? 0 : ((K == 4) ? 1536 : 2816);
            const int P   = 9 - K;
            const int kk0 = (K == 3) ? 0 : ((K == 4) ? 3 : 7);
            #pragma unroll
            for (int k = 0; k < 5; k++) {
                if (k >= K) break;
                int p = c - k;
                if (p < 0 || p > P - 1) continue;
                int kk = kk0 + k;
                #pragma unroll 4
                for (int nl = 0; nl < 16; nl++) {
                    int feat = off + (n0 + nl) * P + p;
                    float w2 = W2[feat * NCLS + cls];
                    const float4* r4 = (const float4*)&sr[(nl * 12 + kk) * 16];
                    float4 a = r4[0], b = r4[1], cc = r4[2], d = r4[3];
                    vac[0]  += a.x * w2;  vac[1]  += a.y * w2;
                    vac[2]  += a.z * w2;  vac[3]  += a.w * w2;
                    vac[4]  += b.x * w2;  vac[5]  += b.y * w2;
                    vac[6]  += b.z * w2;  vac[7]  += b.w * w2;
                    vac[8]  += cc.x * w2; vac[9]  += cc.y * w2;
                    vac[10] += cc.z * w2; vac[11] += cc.w * w2;
                    vac[12] += d.x * w2;  vac[13] += d.y * w2;
                    vac[14] += d.z * w2;  vac[15] += d.w * w2;
                }
            }
        }
        #pragma unroll
        for (int j = 0; j < 16; j++)
            atomicAdd(&g_V[(c * 16 + j) * NCLS + cls], vac[j]);
    }
}

// ---------------------------------------------------------------------------
// K3: per-batch-row. One warp per b (512 blocks x 8 warps).
//     lanes 0..7: compute idx[c] via embed->h4->sign->argmax.
//     all lanes: logits = b2 + sum_h V[h,idx_h,:], then log_softmax.
// ---------------------------------------------------------------------------
__global__ void k3_main(const void* __restrict__ xraw,
                        const float* __restrict__ len_emb,
                        const float* __restrict__ ipd_emb,
                        const float* __restrict__ W1, const float* __restrict__ b1,
                        const float* __restrict__ S,  const float* __restrict__ T,
                        const float* __restrict__ H,  const float* __restrict__ b2,
                        float* __restrict__ out)
{
    __shared__ float sW1[128], sb1[4], sS[480], sT[120], sH[240], sb2[NCLS];
    const int tid = threadIdx.x;
    if (tid < 128) sW1[tid] = W1[tid];
    if (tid < 4)   sb1[tid] = b1[tid];
    for (int i = tid; i < 480; i += 256) sS[i] = S[i];
    if (tid < 120) sT[tid] = T[tid];
    if (tid < 240) sH[tid] = H[tid];
    if (tid < NCLS) sb2[tid] = b2[tid];
    __syncthreads();

    const int warp = tid >> 5, lane = tid & 31;
    const int b = blockIdx.x * 8 + warp;
    const int is64 = g_x64;

    int idx = 0;
    if (lane < 8) {
        const int c = lane;
        int i0, i1;
        if (is64) {
            const long long* xp = (const long long*)xraw;
            i0 = (int)xp[((size_t)b * 8 + c) * 2];
            i1 = (int)xp[((size_t)b * 8 + c) * 2 + 1];
        } else {
            const int* xp = (const int*)xraw;
            i0 = xp[((size_t)b * 8 + c) * 2];
            i1 = xp[((size_t)b * 8 + c) * 2 + 1];
        }

        float h4[4] = {0.f, 0.f, 0.f, 0.f};
        const float4* le4 = (const float4*)(len_emb + (size_t)i0 * 16);
        #pragma unroll
        for (int q = 0; q < 4; q++) {
            float4 v = le4[q];
            const float vv[4] = {v.x, v.y, v.z, v.w};
            #pragma unroll
            for (int s = 0; s < 4; s++) {
                int i = q * 4 + s;
                #pragma unroll
                for (int d = 0; d < 4; d++) h4[d] += vv[s] * sW1[i * 4 + d];
            }
        }
        const float4* ie4 = (const float4*)(ipd_emb + (size_t)i1 * 16);
        #pragma unroll
        for (int q = 0; q < 4; q++) {
            float4 v = ie4[q];
            const float vv[4] = {v.x, v.y, v.z, v.w};
            #pragma unroll
            for (int s = 0; s < 4; s++) {
                int i = 16 + q * 4 + s;
                #pragma unroll
                for (int d = 0; d < 4; d++) h4[d] += vv[s] * sW1[i * 4 + d];
            }
        }
        #pragma unroll
        for (int d = 0; d < 4; d++) h4[d] += sb1[d];

        float m16[16];
        #pragma unroll
        for (int j = 0; j < 16; j++) m16[j] = 0.f;

        #pragma unroll
        for (int k = 0; k < 15; k++) {
            float acc = 0.f;
            #pragma unroll
            for (int d = 0; d < 4; d++) acc += h4[d] * sS[(c * 4 + d) * 15 + k];
            float m = (acc - sT[c * 15 + k]) - 1e-4f;
            float sgn = (m > 0.f) ? 1.f : ((m < 0.f) ? -1.f : 0.f);
            #pragma unroll
            for (int j = 0; j < 16; j++) m16[j] += sgn * sH[k * 16 + j];
        }

        float bm = m16[0];
        #pragma unroll
        for (int j = 1; j < 16; j++)
            if (m16[j] > bm) { bm = m16[j]; idx = j; }   // first-max (strict >)
    }

    // broadcast idx[0..7], build V row offsets
    int vrow[8];
    #pragma unroll
    for (int h = 0; h < 8; h++) {
        int ih = __shfl_sync(0xffffffffu, idx, h);
        vrow[h] = (h * 16 + ih) * NCLS;
    }

    float lg[4];
    #pragma unroll
    for (int t = 0; t < 4; t++) {
        int cls = lane + 32 * t;
        if (cls < NCLS) {
            float v = sb2[cls];
            #pragma unroll
            for (int h = 0; h < 8; h++) v += g_V[vrow[h] + cls];
            lg[t] = v;
        } else {
            lg[t] = -INFINITY;
        }
    }

    float M = fmaxf(fmaxf(lg[0], lg[1]), fmaxf(lg[2], lg[3]));
    #pragma unroll
    for (int off = 16; off > 0; off >>= 1)
        M = fmaxf(M, __shfl_xor_sync(0xffffffffu, M, off));

    float ss = 0.f;
    #pragma unroll
    for (int t = 0; t < 4; t++) ss += expf(lg[t] - M);   // exp(-inf)=0 for pads
    #pragma unroll
    for (int off = 16; off > 0; off >>= 1)
        ss += __shfl_xor_sync(0xffffffffu, ss, off);

    float lse = M + logf(ss);
    #pragma unroll
    for (int t = 0; t < 4; t++) {
        int cls = lane + 32 * t;
        if (cls < NCLS) out[(size_t)b * NCLS + cls] = lg[t] - lse;
    }
}

// ---------------------------------------------------------------------------
// Launch. Input order: x, len_emb, ipd_emb, W1, b1, We, be, w3, w4, w5,
//                      W2, b2, S, H, T, LUT
// ---------------------------------------------------------------------------
extern "C" void kernel_launch(void* const* d_in, const int* in_sizes, int n_in,
                              void* d_out, int out_size)
{
    (void)in_sizes; (void)n_in; (void)out_size;
    const void*  x       = d_in[0];
    const float* len_emb = (const float*)d_in[1];
    const float* ipd_emb = (const float*)d_in[2];
    const float* W1      = (const float*)d_in[3];
    const float* b1      = (const float*)d_in[4];
    const float* We      = (const float*)d_in[5];
    const float* be      = (const float*)d_in[6];
    const float* w3      = (const float*)d_in[7];
    const float* w4      = (const float*)d_in[8];
    const float* w5      = (const float*)d_in[9];
    const float* W2      = (const float*)d_in[10];
    const float* b2      = (const float*)d_in[11];
    const float* S       = (const float*)d_in[12];
    const float* H       = (const float*)d_in[13];
    const float* T       = (const float*)d_in[14];
    const float* LUT     = (const float*)d_in[15];
    float* out = (float*)d_out;

    k1_wef<<<96, 256>>>(We, be, w3, w4, w5, x);
    k2_v<<<128, 128>>>(LUT, W2);
    k3_main<<<512, 256>>>(x, len_emb, ipd_emb, W1, b1, S, T, H, b2, out);
}

// round 2
// speedup vs baseline: 1.1287x; 1.1287x over previous
#include <cuda_runtime.h>
#include <math.h>

// ---------------------------------------------------------------------------
// Problem constants
//  B=4096, SEQ=C=8, D=4, L=2048, NK=256, NCLS=100
//  filters: w3 (256,3,2048), w4 (256,4,2048), w5 (256,5,2048) -> 3072 rows
//  feature layout: K=3 off 0 (P=6), K=4 off 1536 (P=5), K=5 off 2816 (P=4)
// ---------------------------------------------------------------------------

#define NKK 3072           // total filter rows (n*12 + kk), kk: 0-2 K3, 3-6 K4, 7-11 K5
#define NCLS 100

// Scratch (device globals; no allocations allowed)
__device__ float g_WeF[5 * NKK];      // [d][nkk]; d=4 holds be-projection
__device__ float g_V[8 * 16 * NCLS];  // per (position h, code j) logit contribution
__device__ int   g_x64;               // 1 if x is int64, 0 if int32

// ---------------------------------------------------------------------------
// K1: WeF[d][nkk] = sum_l {We[d,:],be}[l] * w_row[nkk][l]
//     Skinny GEMM 3072x2048 @ 2048x5. DRAM-bound (24 MB filter read).
//     192 blocks x 256 threads; each warp owns 2 filter rows, float4 loads,
//     fully unrolled (high MLP). Also zeroes g_V and detects x dtype.
// ---------------------------------------------------------------------------
__global__ void k1_wef(const float* __restrict__ We, const float* __restrict__ be,
                       const float* __restrict__ w3, const float* __restrict__ w4,
                       const float* __restrict__ w5, const void* __restrict__ xraw)
{
    __shared__ float4 sW4[5 * 512];   // [d][l/4]
    const int tid = threadIdx.x;

    if (blockIdx.x == 0 && tid == 0) {
        // int64 layout -> odd int32 words all zero (values in [0,1500))
        const int* xi = (const int*)xraw;
        int any = 0;
        #pragma unroll 1
        for (int i = 1; i < 256; i += 2) any |= xi[i];
        g_x64 = (any == 0) ? 1 : 0;
    }

    int gz = blockIdx.x * blockDim.x + tid;
    if (gz < 8 * 16 * NCLS) g_V[gz] = 0.f;

    const float4* We4 = (const float4*)We;
    const float4* be4 = (const float4*)be;
    for (int i = tid; i < 512; i += 256) {
        sW4[i]            = We4[i];
        sW4[512 + i]      = We4[512 + i];
        sW4[1024 + i]     = We4[1024 + i];
        sW4[1536 + i]     = We4[1536 + i];
        sW4[2048 + i]     = be4[i];
    }
    __syncthreads();

    const int warp = tid >> 5, lane = tid & 31;
    const int rbase = blockIdx.x * 16 + warp * 2;   // 2 rows per warp

    const float4* rp[2];
    #pragma unroll
    for (int r = 0; r < 2; r++) {
        int rid = rbase + r;
        int n = rid / 12, kk = rid % 12;
        const float* base;
        if (kk < 3)      base = w3 + (size_t)(n * 3 + kk) * 2048;
        else if (kk < 7) base = w4 + (size_t)(n * 4 + (kk - 3)) * 2048;
        else             base = w5 + (size_t)(n * 5 + (kk - 7)) * 2048;
        rp[r] = (const float4*)base;
    }

    float acc[2][5];
    #pragma unroll
    for (int r = 0; r < 2; r++)
        #pragma unroll
        for (int d = 0; d < 5; d++) acc[r][d] = 0.f;

    #pragma unroll
    for (int i = 0; i < 16; i++) {
        const int l = lane + 32 * i;
        float4 f0 = rp[0][l];
        float4 f1 = rp[1][l];
        #pragma unroll
        for (int d = 0; d < 5; d++) {
            float4 s = sW4[d * 512 + l];
            acc[0][d] += f0.x * s.x + f0.y * s.y + f0.z * s.z + f0.w * s.w;
            acc[1][d] += f1.x * s.x + f1.y * s.y + f1.z * s.z + f1.w * s.w;
        }
    }

    #pragma unroll
    for (int r = 0; r < 2; r++)
        #pragma unroll
        for (int d = 0; d < 5; d++)
            #pragma unroll
            for (int off = 16; off > 0; off >>= 1)
                acc[r][d] += __shfl_down_sync(0xffffffffu, acc[r][d], off);

    if (lane == 0) {
        #pragma unroll
        for (int r = 0; r < 2; r++) {
            int rid = rbase + r;
            #pragma unroll
            for (int d = 0; d < 5; d++) g_WeF[d * NKK + rid] = acc[r][d];
        }
    }
}

// ---------------------------------------------------------------------------
// K2: V[c][j][cls] += sum over valid (kk, p=c-k), n-chunk of
//        relu(LUT[c,j,:].WeF[:,nkk] + WeF[4,nkk]) * W2[feat(K,n,p), cls]
//     128 blocks = 8 c x 16 n-chunks(16 each); 128 threads (thread = cls).
// ---------------------------------------------------------------------------
__global__ void k2_v(const float* __restrict__ LUT, const float* __restrict__ W2)
{
    __shared__ float sr[192 * 16];   // [n_local*12 + kk][j]
    __shared__ float sLUT[64];       // LUT[c][j][d]
    const int tid = threadIdx.x;     // 128
    const int c  = blockIdx.x >> 4;
    const int n0 = (blockIdx.x & 15) * 16;

    if (tid < 64) sLUT[tid] = LUT[c * 64 + tid];
    __syncthreads();

    for (int pr = tid; pr < 192; pr += 128) {
        int nl = pr / 12, kk = pr % 12;
        int nkk = (n0 + nl) * 12 + kk;
        float v0 = g_WeF[nkk];
        float v1 = g_WeF[NKK + nkk];
        float v2 = g_WeF[2 * NKK + nkk];
        float v3 = g_WeF[3 * NKK + nkk];
        float v4 = g_WeF[4 * NKK + nkk];
        #pragma unroll
        for (int j = 0; j < 16; j++) {
            float r = sLUT[j * 4] * v0 + sLUT[j * 4 + 1] * v1 +
                      sLUT[j * 4 + 2] * v2 + sLUT[j * 4 + 3] * v3 + v4;
            sr[pr * 16 + j] = fmaxf(r, 0.f);
        }
    }
    __syncthreads();

    if (tid < NCLS) {
        const int cls = tid;
        float vac[16];
        #pragma unroll
        for (int j = 0; j < 16; j++) vac[j] = 0.f;

        #pragma unroll
        for (int K = 3; K <= 5; K++) {
            const int off = (K == 3) ? 0 : ((K == 4) ? 1536 : 2816);
            const int P   = 9 - K;
            const int kk0 = (K == 3) ? 0 : ((K == 4) ? 3 : 7);
            #pragma unroll
            for (int k = 0; k < 5; k++) {
                if (k >= K) break;
                int p = c - k;
                if (p < 0 || p > P - 1) continue;
                int kk = kk0 + k;
                #pragma unroll 4
                for (int nl = 0; nl < 16; nl++) {
                    int feat = off + (n0 + nl) * P + p;
                    float w2 = W2[feat * NCLS + cls];
                    const float4* r4 = (const float4*)&sr[(nl * 12 + kk) * 16];
                    float4 a = r4[0], b = r4[1], cc = r4[2], d = r4[3];
                    vac[0]  += a.x * w2;  vac[1]  += a.y * w2;
                    vac[2]  += a.z * w2;  vac[3]  += a.w * w2;
                    vac[4]  += b.x * w2;  vac[5]  += b.y * w2;
                    vac[6]  += b.z * w2;  vac[7]  += b.w * w2;
                    vac[8]  += cc.x * w2; vac[9]  += cc.y * w2;
                    vac[10] += cc.z * w2; vac[11] += cc.w * w2;
                    vac[12] += d.x * w2;  vac[13] += d.y * w2;
                    vac[14] += d.z * w2;  vac[15] += d.w * w2;
                }
            }
        }
        #pragma unroll
        for (int j = 0; j < 16; j++)
            atomicAdd(&g_V[(c * 16 + j) * NCLS + cls], vac[j]);
    }
}

// ---------------------------------------------------------------------------
// K3: per-batch-row. One warp per b (512 blocks x 8 warps).
//     lanes 0..7: compute idx[c] via embed->h4->sign->argmax.
//     all lanes: logits = b2 + sum_h V[h,idx_h,:], then log_softmax.
// ---------------------------------------------------------------------------
__global__ void k3_main(const void* __restrict__ xraw,
                        const float* __restrict__ len_emb,
                        const float* __restrict__ ipd_emb,
                        const float* __restrict__ W1, const float* __restrict__ b1,
                        const float* __restrict__ S,  const float* __restrict__ T,
                        const float* __restrict__ H,  const float* __restrict__ b2,
                        float* __restrict__ out)
{
    __shared__ float sW1[128], sb1[4], sS[480], sT[120], sH[240], sb2[NCLS];
    const int tid = threadIdx.x;
    if (tid < 128) sW1[tid] = W1[tid];
    if (tid < 4)   sb1[tid] = b1[tid];
    for (int i = tid; i < 480; i += 256) sS[i] = S[i];
    if (tid < 120) sT[tid] = T[tid];
    if (tid < 240) sH[tid] = H[tid];
    if (tid < NCLS) sb2[tid] = b2[tid];
    __syncthreads();

    const int warp = tid >> 5, lane = tid & 31;
    const int b = blockIdx.x * 8 + warp;
    const int is64 = g_x64;

    int idx = 0;
    if (lane < 8) {
        const int c = lane;
        int i0, i1;
        if (is64) {
            const long long* xp = (const long long*)xraw;
            i0 = (int)xp[((size_t)b * 8 + c) * 2];
            i1 = (int)xp[((size_t)b * 8 + c) * 2 + 1];
        } else {
            const int* xp = (const int*)xraw;
            i0 = xp[((size_t)b * 8 + c) * 2];
            i1 = xp[((size_t)b * 8 + c) * 2 + 1];
        }

        float h4[4] = {0.f, 0.f, 0.f, 0.f};
        const float4* le4 = (const float4*)(len_emb + (size_t)i0 * 16);
        #pragma unroll
        for (int q = 0; q < 4; q++) {
            float4 v = le4[q];
            const float vv[4] = {v.x, v.y, v.z, v.w};
            #pragma unroll
            for (int s = 0; s < 4; s++) {
                int i = q * 4 + s;
                #pragma unroll
                for (int d = 0; d < 4; d++) h4[d] += vv[s] * sW1[i * 4 + d];
            }
        }
        const float4* ie4 = (const float4*)(ipd_emb + (size_t)i1 * 16);
        #pragma unroll
        for (int q = 0; q < 4; q++) {
            float4 v = ie4[q];
            const float vv[4] = {v.x, v.y, v.z, v.w};
            #pragma unroll
            for (int s = 0; s < 4; s++) {
                int i = 16 + q * 4 + s;
                #pragma unroll
                for (int d = 0; d < 4; d++) h4[d] += vv[s] * sW1[i * 4 + d];
            }
        }
        #pragma unroll
        for (int d = 0; d < 4; d++) h4[d] += sb1[d];

        float m16[16];
        #pragma unroll
        for (int j = 0; j < 16; j++) m16[j] = 0.f;

        #pragma unroll
        for (int k = 0; k < 15; k++) {
            float acc = 0.f;
            #pragma unroll
            for (int d = 0; d < 4; d++) acc += h4[d] * sS[(c * 4 + d) * 15 + k];
            float m = (acc - sT[c * 15 + k]) - 1e-4f;
            float sgn = (m > 0.f) ? 1.f : ((m < 0.f) ? -1.f : 0.f);
            #pragma unroll
            for (int j = 0; j < 16; j++) m16[j] += sgn * sH[k * 16 + j];
        }

        float bm = m16[0];
        #pragma unroll
        for (int j = 1; j < 16; j++)
            if (m16[j] > bm) { bm = m16[j]; idx = j; }   // first-max (strict >)
    }

    // broadcast idx[0..7], build V row offsets
    int vrow[8];
    #pragma unroll
    for (int h = 0; h < 8; h++) {
        int ih = __shfl_sync(0xffffffffu, idx, h);
        vrow[h] = (h * 16 + ih) * NCLS;
    }

    float lg[4];
    #pragma unroll
    for (int t = 0; t < 4; t++) {
        int cls = lane + 32 * t;
        if (cls < NCLS) {
            float v = sb2[cls];
            #pragma unroll
            for (int h = 0; h < 8; h++) v += g_V[vrow[h] + cls];
            lg[t] = v;
        } else {
            lg[t] = -INFINITY;
        }
    }

    float M = fmaxf(fmaxf(lg[0], lg[1]), fmaxf(lg[2], lg[3]));
    #pragma unroll
    for (int off = 16; off > 0; off >>= 1)
        M = fmaxf(M, __shfl_xor_sync(0xffffffffu, M, off));

    float ss = 0.f;
    #pragma unroll
    for (int t = 0; t < 4; t++) ss += expf(lg[t] - M);   // exp(-inf)=0 for pads
    #pragma unroll
    for (int off = 16; off > 0; off >>= 1)
        ss += __shfl_xor_sync(0xffffffffu, ss, off);

    float lse = M + logf(ss);
    #pragma unroll
    for (int t = 0; t < 4; t++) {
        int cls = lane + 32 * t;
        if (cls < NCLS) out[(size_t)b * NCLS + cls] = lg[t] - lse;
    }
}

// ---------------------------------------------------------------------------
// Launch. Input order: x, len_emb, ipd_emb, W1, b1, We, be, w3, w4, w5,
//                      W2, b2, S, H, T, LUT
// ---------------------------------------------------------------------------
extern "C" void kernel_launch(void* const* d_in, const int* in_sizes, int n_in,
                              void* d_out, int out_size)
{
    (void)in_sizes; (void)n_in; (void)out_size;
    const void*  x       = d_in[0];
    const float* len_emb = (const float*)d_in[1];
    const float* ipd_emb = (const float*)d_in[2];
    const float* W1      = (const float*)d_in[3];
    const float* b1      = (const float*)d_in[4];
    const float* We      = (const float*)d_in[5];
    const float* be      = (const float*)d_in[6];
    const float* w3      = (const float*)d_in[7];
    const float* w4      = (const float*)d_in[8];
    const float* w5      = (const float*)d_in[9];
    const float* W2      = (const float*)d_in[10];
    const float* b2      = (const float*)d_in[11];
    const float* S       = (const float*)d_in[12];
    const float* H       = (const float*)d_in[13];
    const float* T       = (const float*)d_in[14];
    const float* LUT     = (const float*)d_in[15];
    float* out = (float*)d_out;

    k1_wef<<<192, 256>>>(We, be, w3, w4, w5, x);
    k2_v<<<128, 128>>>(LUT, W2);
    k3_main<<<512, 256>>>(x, len_emb, ipd_emb, W1, b1, S, T, H, b2, out);
}

// round 3
// speedup vs baseline: 1.1880x; 1.0525x over previous
#include <cuda_runtime.h>
#include <math.h>

// ---------------------------------------------------------------------------
// Problem constants
//  B=4096, SEQ=C=8, D=4, L=2048, NK=256, NCLS=100
//  filters: w3 (256,3,2048), w4 (256,4,2048), w5 (256,5,2048) -> 3072 rows
// ---------------------------------------------------------------------------

#define NKK 3072           // total filter rows (n*12 + kk), kk: 0-2 K3, 3-6 K4, 7-11 K5
#define NCLS 100

__device__ float g_WeF[5 * NKK];      // [d][nkk]; d=4 holds be-projection
__device__ float g_V[8 * 16 * NCLS];  // per (position h, code j) logit contribution
__device__ int   g_x64;               // 1 if x is int64, 0 if int32

// ---------------------------------------------------------------------------
// K1: WeF[d][nkk] = sum_l {We[d,:],be}[l] * w_row[nkk][l]
//     DRAM-bound 24 MB read. 384 blocks x 128 threads; warp owns 2 rows;
//     ALL 32 float4 loads per lane issued up-front (high MLP), then FMA.
// ---------------------------------------------------------------------------
__global__ void __launch_bounds__(128, 1)
k1_wef(const float* __restrict__ We, const float* __restrict__ be,
       const float* __restrict__ w3, const float* __restrict__ w4,
       const float* __restrict__ w5, const void* __restrict__ xraw)
{
    __shared__ float4 sW4[5 * 512];   // [d][l/4]
    const int tid = threadIdx.x;

    if (blockIdx.x == 0 && tid == 0) {
        // int64 layout -> odd int32 words all zero (values in [0,1500))
        const int* xi = (const int*)xraw;
        int any = 0;
        #pragma unroll 1
        for (int i = 1; i < 256; i += 2) any |= xi[i];
        g_x64 = (any == 0) ? 1 : 0;
    }

    for (int gz = blockIdx.x * 128 + tid; gz < 8 * 16 * NCLS; gz += 384 * 128)
        g_V[gz] = 0.f;

    const float4* We4 = (const float4*)We;
    const float4* be4 = (const float4*)be;
    for (int i = tid; i < 512; i += 128) {
        sW4[i]        = We4[i];
        sW4[512 + i]  = We4[512 + i];
        sW4[1024 + i] = We4[1024 + i];
        sW4[1536 + i] = We4[1536 + i];
        sW4[2048 + i] = be4[i];
    }

    const int warp = tid >> 5, lane = tid & 31;
    const int rbase = blockIdx.x * 8 + warp * 2;   // 2 rows per warp

    const float4* rp[2];
    #pragma unroll
    for (int r = 0; r < 2; r++) {
        int rid = rbase + r;
        int n = rid / 12, kk = rid % 12;
        const float* base;
        if (kk < 3)      base = w3 + (size_t)(n * 3 + kk) * 2048;
        else if (kk < 7) base = w4 + (size_t)(n * 4 + (kk - 3)) * 2048;
        else             base = w5 + (size_t)(n * 5 + (kk - 7)) * 2048;
        rp[r] = (const float4*)base;
    }

    // Front-batched loads: 32 LDG.128 per lane in flight.
    float4 fA[16], fB[16];
    #pragma unroll
    for (int i = 0; i < 16; i++) {
        fA[i] = rp[0][lane + 32 * i];
        fB[i] = rp[1][lane + 32 * i];
    }

    __syncthreads();   // sW4 ready (loads above don't depend on it)

    float acc[2][5];
    #pragma unroll
    for (int r = 0; r < 2; r++)
        #pragma unroll
        for (int d = 0; d < 5; d++) acc[r][d] = 0.f;

    #pragma unroll
    for (int i = 0; i < 16; i++) {
        const int l = lane + 32 * i;
        #pragma unroll
        for (int d = 0; d < 5; d++) {
            float4 s = sW4[d * 512 + l];
            acc[0][d] += fA[i].x * s.x + fA[i].y * s.y + fA[i].z * s.z + fA[i].w * s.w;
            acc[1][d] += fB[i].x * s.x + fB[i].y * s.y + fB[i].z * s.z + fB[i].w * s.w;
        }
    }

    #pragma unroll
    for (int r = 0; r < 2; r++)
        #pragma unroll
        for (int d = 0; d < 5; d++)
            #pragma unroll
            for (int off = 16; off > 0; off >>= 1)
                acc[r][d] += __shfl_down_sync(0xffffffffu, acc[r][d], off);

    if (lane == 0) {
        #pragma unroll
        for (int r = 0; r < 2; r++) {
            int rid = rbase + r;
            #pragma unroll
            for (int d = 0; d < 5; d++) g_WeF[d * NKK + rid] = acc[r][d];
        }
    }
}

// ---------------------------------------------------------------------------
// K2: V[c][j][cls] += sum over valid (kk, p=c-k), n-chunk of
//        relu(LUT[c,j,:].WeF[:,nkk] + WeF[4,nkk]) * W2[feat(K,n,p), cls]
//     128 blocks = 8 c x 16 n-chunks(16 each); 128 threads (thread = cls).
// ---------------------------------------------------------------------------
__global__ void k2_v(const float* __restrict__ LUT, const float* __restrict__ W2)
{
    __shared__ float sr[192 * 16];   // [n_local*12 + kk][j]
    __shared__ float sLUT[64];       // LUT[c][j][d]
    const int tid = threadIdx.x;     // 128
    const int c  = blockIdx.x >> 4;
    const int n0 = (blockIdx.x & 15) * 16;

    if (tid < 64) sLUT[tid] = LUT[c * 64 + tid];
    __syncthreads();

    for (int pr = tid; pr < 192; pr += 128) {
        int nl = pr / 12, kk = pr % 12;
        int nkk = (n0 + nl) * 12 + kk;
        float v0 = g_WeF[nkk];
        float v1 = g_WeF[NKK + nkk];
        float v2 = g_WeF[2 * NKK + nkk];
        float v3 = g_WeF[3 * NKK + nkk];
        float v4 = g_WeF[4 * NKK + nkk];
        #pragma unroll
        for (int j = 0; j < 16; j++) {
            float r = sLUT[j * 4] * v0 + sLUT[j * 4 + 1] * v1 +
                      sLUT[j * 4 + 2] * v2 + sLUT[j * 4 + 3] * v3 + v4;
            sr[pr * 16 + j] = fmaxf(r, 0.f);
        }
    }
    __syncthreads();

    if (tid < NCLS) {
        const int cls = tid;
        float vac[16];
        #pragma unroll
        for (int j = 0; j < 16; j++) vac[j] = 0.f;

        #pragma unroll
        for (int K = 3; K <= 5; K++) {
            const int off = (K == 3) ? 0 : ((K == 4) ? 1536 : 2816);
            const int P   = 9 - K;
            const int kk0 = (K == 3) ? 0 : ((K == 4) ? 3 : 7);
            #pragma unroll
            for (int k = 0; k < 5; k++) {
                if (k >= K) break;
                int p = c - k;
                if (p < 0 || p > P - 1) continue;
                int kk = kk0 + k;
                #pragma unroll 4
                for (int nl = 0; nl < 16; nl++) {
                    int feat = off + (n0 + nl) * P + p;
                    float w2 = W2[feat * NCLS + cls];
                    const float4* r4 = (const float4*)&sr[(nl * 12 + kk) * 16];
                    float4 a = r4[0], b = r4[1], cc = r4[2], d = r4[3];
                    vac[0]  += a.x * w2;  vac[1]  += a.y * w2;
                    vac[2]  += a.z * w2;  vac[3]  += a.w * w2;
                    vac[4]  += b.x * w2;  vac[5]  += b.y * w2;
                    vac[6]  += b.z * w2;  vac[7]  += b.w * w2;
                    vac[8]  += cc.x * w2; vac[9]  += cc.y * w2;
                    vac[10] += cc.z * w2; vac[11] += cc.w * w2;
                    vac[12] += d.x * w2;  vac[13] += d.y * w2;
                    vac[14] += d.z * w2;  vac[15] += d.w * w2;
                }
            }
        }
        #pragma unroll
        for (int j = 0; j < 16; j++)
            atomicAdd(&g_V[(c * 16 + j) * NCLS + cls], vac[j]);
    }
}

// ---------------------------------------------------------------------------
// K3: per-batch-row. One warp per b (512 blocks x 8 warps).
// ---------------------------------------------------------------------------
__global__ void k3_main(const void* __restrict__ xraw,
                        const float* __restrict__ len_emb,
                        const float* __restrict__ ipd_emb,
                        const float* __restrict__ W1, const float* __restrict__ b1,
                        const float* __restrict__ S,  const float* __restrict__ T,
                        const float* __restrict__ H,  const float* __restrict__ b2,
                        float* __restrict__ out)
{
    __shared__ float sW1[128], sb1[4], sS[480], sT[120], sH[240], sb2[NCLS];
    const int tid = threadIdx.x;
    if (tid < 128) sW1[tid] = W1[tid];
    if (tid < 4)   sb1[tid] = b1[tid];
    for (int i = tid; i < 480; i += 256) sS[i] = S[i];
    if (tid < 120) sT[tid] = T[tid];
    if (tid < 240) sH[tid] = H[tid];
    if (tid < NCLS) sb2[tid] = b2[tid];
    __syncthreads();

    const int warp = tid >> 5, lane = tid & 31;
    const int b = blockIdx.x * 8 + warp;
    const int is64 = g_x64;

    int idx = 0;
    if (lane < 8) {
        const int c = lane;
        int i0, i1;
        if (is64) {
            const long long* xp = (const long long*)xraw;
            i0 = (int)xp[((size_t)b * 8 + c) * 2];
            i1 = (int)xp[((size_t)b * 8 + c) * 2 + 1];
        } else {
            const int* xp = (const int*)xraw;
            i0 = xp[((size_t)b * 8 + c) * 2];
            i1 = xp[((size_t)b * 8 + c) * 2 + 1];
        }

        float h4[4] = {0.f, 0.f, 0.f, 0.f};
        const float4* le4 = (const float4*)(len_emb + (size_t)i0 * 16);
        #pragma unroll
        for (int q = 0; q < 4; q++) {
            float4 v = le4[q];
            const float vv[4] = {v.x, v.y, v.z, v.w};
            #pragma unroll
            for (int s = 0; s < 4; s++) {
                int i = q * 4 + s;
                #pragma unroll
                for (int d = 0; d < 4; d++) h4[d] += vv[s] * sW1[i * 4 + d];
            }
        }
        const float4* ie4 = (const float4*)(ipd_emb + (size_t)i1 * 16);
        #pragma unroll
        for (int q = 0; q < 4; q++) {
            float4 v = ie4[q];
            const float vv[4] = {v.x, v.y, v.z, v.w};
            #pragma unroll
            for (int s = 0; s < 4; s++) {
                int i = 16 + q * 4 + s;
                #pragma unroll
                for (int d = 0; d < 4; d++) h4[d] += vv[s] * sW1[i * 4 + d];
            }
        }
        #pragma unroll
        for (int d = 0; d < 4; d++) h4[d] += sb1[d];

        float m16[16];
        #pragma unroll
        for (int j = 0; j < 16; j++) m16[j] = 0.f;

        #pragma unroll
        for (int k = 0; k < 15; k++) {
            float acc = 0.f;
            #pragma unroll
            for (int d = 0; d < 4; d++) acc += h4[d] * sS[(c * 4 + d) * 15 + k];
            float m = (acc - sT[c * 15 + k]) - 1e-4f;
            float sgn = (m > 0.f) ? 1.f : ((m < 0.f) ? -1.f : 0.f);
            #pragma unroll
            for (int j = 0; j < 16; j++) m16[j] += sgn * sH[k * 16 + j];
        }

        float bm = m16[0];
        #pragma unroll
        for (int j = 1; j < 16; j++)
            if (m16[j] > bm) { bm = m16[j]; idx = j; }   // first-max (strict >)
    }

    int vrow[8];
    #pragma unroll
    for (int h = 0; h < 8; h++) {
        int ih = __shfl_sync(0xffffffffu, idx, h);
        vrow[h] = (h * 16 + ih) * NCLS;
    }

    float lg[4];
    #pragma unroll
    for (int t = 0; t < 4; t++) {
        int cls = lane + 32 * t;
        if (cls < NCLS) {
            float v = sb2[cls];
            #pragma unroll
            for (int h = 0; h < 8; h++) v += g_V[vrow[h] + cls];
            lg[t] = v;
        } else {
            lg[t] = -INFINITY;
        }
    }

    float M = fmaxf(fmaxf(lg[0], lg[1]), fmaxf(lg[2], lg[3]));
    #pragma unroll
    for (int off = 16; off > 0; off >>= 1)
        M = fmaxf(M, __shfl_xor_sync(0xffffffffu, M, off));

    float ss = 0.f;
    #pragma unroll
    for (int t = 0; t < 4; t++) ss += expf(lg[t] - M);
    #pragma unroll
    for (int off = 16; off > 0; off >>= 1)
        ss += __shfl_xor_sync(0xffffffffu, ss, off);

    float lse = M + logf(ss);
    #pragma unroll
    for (int t = 0; t < 4; t++) {
        int cls = lane + 32 * t;
        if (cls < NCLS) out[(size_t)b * NCLS + cls] = lg[t] - lse;
    }
}

// ---------------------------------------------------------------------------
extern "C" void kernel_launch(void* const* d_in, const int* in_sizes, int n_in,
                              void* d_out, int out_size)
{
    (void)in_sizes; (void)n_in; (void)out_size;
    const void*  x       = d_in[0];
    const float* len_emb = (const float*)d_in[1];
    const float* ipd_emb = (const float*)d_in[2];
    const float* W1      = (const float*)d_in[3];
    const float* b1      = (const float*)d_in[4];
    const float* We      = (const float*)d_in[5];
    const float* be      = (const float*)d_in[6];
    const float* w3      = (const float*)d_in[7];
    const float* w4      = (const float*)d_in[8];
    const float* w5      = (const float*)d_in[9];
    const float* W2      = (const float*)d_in[10];
    const float* b2      = (const float*)d_in[11];
    const float* S       = (const float*)d_in[12];
    const float* H       = (const float*)d_in[13];
    const float* T       = (const float*)d_in[14];
    const float* LUT     = (const float*)d_in[15];
    float* out = (float*)d_out;

    k1_wef<<<384, 128>>>(We, be, w3, w4, w5, x);
    k2_v<<<128, 128>>>(LUT, W2);
    k3_main<<<512, 256>>>(x, len_emb, ipd_emb, W1, b1, S, T, H, b2, out);
}